// round 4
// baseline (speedup 1.0000x reference)
#include <cuda_runtime.h>

#define NN   10000
#define DEG  32
#define DIM  256
#define NHEADS 8
#define HDIM 32
#define NE   (NN*DEG)

// Scratch for projected Q/K/V (no cudaMalloc allowed)
__device__ float g_Q[NN * DIM];
__device__ float g_K[NN * DIM];
__device__ float g_V[NN * DIM];

// ---------------------------------------------------------------------------
// Kernel 1: Q/K/V projections.  C = x @ W, W selected by blockIdx.z.
// 64x64 tile, BK=16, 256 threads, 4x4 micro-tile.
// ---------------------------------------------------------------------------
__global__ __launch_bounds__(256) void qkv_kernel(
    const float* __restrict__ x,
    const float* __restrict__ WQ,
    const float* __restrict__ WK,
    const float* __restrict__ WV)
{
    const float* W = (blockIdx.z == 0) ? WQ : (blockIdx.z == 1) ? WK : WV;
    float* C       = (blockIdx.z == 0) ? g_Q : (blockIdx.z == 1) ? g_K : g_V;

    __shared__ float As[16][68];   // [k][m], padded
    __shared__ float Bs[16][68];   // [k][n]

    const int tid = threadIdx.x;
    const int tx = tid & 15, ty = tid >> 4;
    const int m0 = blockIdx.x * 64, n0 = blockIdx.y * 64;

    float acc[4][4] = {};

    for (int k0 = 0; k0 < DIM; k0 += 16) {
        // x tile: 64 rows x 16 cols, transposed store
        {
            int r = tid >> 2;
            int c = (tid & 3) << 2;
            float4 v = make_float4(0.f, 0.f, 0.f, 0.f);
            int gm = m0 + r;
            if (gm < NN) v = *(const float4*)(x + (size_t)gm * DIM + k0 + c);
            As[c + 0][r] = v.x; As[c + 1][r] = v.y;
            As[c + 2][r] = v.z; As[c + 3][r] = v.w;
        }
        // W tile: 16 rows x 64 cols
        {
            int wr = tid >> 4, wc = (tid & 15) << 2;
            *(float4*)&Bs[wr][wc] = *(const float4*)(W + (size_t)(k0 + wr) * DIM + n0 + wc);
        }
        __syncthreads();

        #pragma unroll
        for (int k = 0; k < 16; k++) {
            float4 a = *(float4*)&As[k][ty << 2];
            float4 b = *(float4*)&Bs[k][tx << 2];
            acc[0][0] += a.x * b.x; acc[0][1] += a.x * b.y; acc[0][2] += a.x * b.z; acc[0][3] += a.x * b.w;
            acc[1][0] += a.y * b.x; acc[1][1] += a.y * b.y; acc[1][2] += a.y * b.z; acc[1][3] += a.y * b.w;
            acc[2][0] += a.z * b.x; acc[2][1] += a.z * b.y; acc[2][2] += a.z * b.z; acc[2][3] += a.z * b.w;
            acc[3][0] += a.w * b.x; acc[3][1] += a.w * b.y; acc[3][2] += a.w * b.z; acc[3][3] += a.w * b.w;
        }
        __syncthreads();
    }

    #pragma unroll
    for (int i = 0; i < 4; i++) {
        int gm = m0 + (ty << 2) + i;
        if (gm < NN) {
            float4 v = make_float4(acc[i][0], acc[i][1], acc[i][2], acc[i][3]);
            *(float4*)(C + (size_t)gm * DIM + n0 + (tx << 2)) = v;
        }
    }
}

// ---------------------------------------------------------------------------
// Kernel 2: fused edge pipeline.
// One block = 128 consecutive edges (4 complete nodes) x 2 heads (64 E1 cols).
//   Phase 1: E1 tile GEMM (edge_attr @ WE1 cols) + fused E2 dot.
//   Phase 2: score = sum_k E1 * K[nbr] * Q[node] (+E2), clip.
//   Phase 3: softmax over deg=32 per (node, head), warp-level.
//   Phase 4: out = attn @ V[nbr].
// ---------------------------------------------------------------------------
__global__ __launch_bounds__(256) void edge_kernel(
    const float* __restrict__ ea,
    const int* __restrict__ eidx,       // edge_index row 0 = neighbors (int32!)
    const float* __restrict__ WE1,
    const float* __restrict__ WE2,
    const float* __restrict__ bE2,
    float* __restrict__ out)
{
    const int hg   = blockIdx.x;        // head-group 0..3 (heads 2hg, 2hg+1)
    const int tile = blockIdx.y;        // 0..2499
    const int e0   = tile * 128;
    const int ncol0 = hg * 64;          // E1 / QKV column offset

    __shared__ float As[16][132];       // ea chunk [c][e]
    __shared__ float Bs[16][68];        // WE1 chunk [c][n]
    __shared__ float W2s[16][2];        // WE2 chunk
    __shared__ float sc[2][128];        // scores -> attn
    __shared__ float e2s[2][128];
    __shared__ int   nb[128];

    const int tid = threadIdx.x;
    const int tx = tid & 15, ty = tid >> 4;

    if (tid < 128) nb[tid] = eidx[e0 + tid];

    float acc[8][4] = {};
    float e2acc = 0.f;
    const int e2e = tid & 127, e2h = tid >> 7;

    for (int k0 = 0; k0 < DIM; k0 += 16) {
        // edge_attr tile: 128 x 16 (transposed into As)
        #pragma unroll
        for (int l = 0; l < 2; l++) {
            int idx = tid + l * 256;
            int r = idx >> 2;
            int c = (idx & 3) << 2;
            float4 v = *(const float4*)(ea + (size_t)(e0 + r) * DIM + k0 + c);
            As[c + 0][r] = v.x; As[c + 1][r] = v.y;
            As[c + 2][r] = v.z; As[c + 3][r] = v.w;
        }
        // WE1 tile: 16 x 64
        {
            int wr = tid >> 4, wc = (tid & 15) << 2;
            *(float4*)&Bs[wr][wc] = *(const float4*)(WE1 + (size_t)(k0 + wr) * DIM + ncol0 + wc);
        }
        // WE2 tile: 16 x 2
        if (tid < 32) {
            int wr = tid >> 1, wc = tid & 1;
            W2s[wr][wc] = WE2[(k0 + wr) * NHEADS + hg * 2 + wc];
        }
        __syncthreads();

        #pragma unroll
        for (int k = 0; k < 16; k++) {
            float4 a0 = *(float4*)&As[k][ty << 3];
            float4 a1 = *(float4*)&As[k][(ty << 3) + 4];
            float4 b  = *(float4*)&Bs[k][tx << 2];
            acc[0][0] += a0.x * b.x; acc[0][1] += a0.x * b.y; acc[0][2] += a0.x * b.z; acc[0][3] += a0.x * b.w;
            acc[1][0] += a0.y * b.x; acc[1][1] += a0.y * b.y; acc[1][2] += a0.y * b.z; acc[1][3] += a0.y * b.w;
            acc[2][0] += a0.z * b.x; acc[2][1] += a0.z * b.y; acc[2][2] += a0.z * b.z; acc[2][3] += a0.z * b.w;
            acc[3][0] += a0.w * b.x; acc[3][1] += a0.w * b.y; acc[3][2] += a0.w * b.z; acc[3][3] += a0.w * b.w;
            acc[4][0] += a1.x * b.x; acc[4][1] += a1.x * b.y; acc[4][2] += a1.x * b.z; acc[4][3] += a1.x * b.w;
            acc[5][0] += a1.y * b.x; acc[5][1] += a1.y * b.y; acc[5][2] += a1.y * b.z; acc[5][3] += a1.y * b.w;
            acc[6][0] += a1.z * b.x; acc[6][1] += a1.z * b.y; acc[6][2] += a1.z * b.z; acc[6][3] += a1.z * b.w;
            acc[7][0] += a1.w * b.x; acc[7][1] += a1.w * b.y; acc[7][2] += a1.w * b.z; acc[7][3] += a1.w * b.w;
        }
        // fused E2 partial: one (edge, head) pair per thread
        #pragma unroll
        for (int k = 0; k < 16; k++) e2acc += As[k][e2e] * W2s[k][e2h];
        __syncthreads();
    }

    e2s[e2h][e2e] = e2acc + bE2[hg * 2 + e2h];
    __syncthreads();

    // ---- Phase 2: scores --------------------------------------------------
    const int node_l = ty >> 2;                 // local node 0..3
    const int node   = tile * 4 + node_l;
    const float4 q4 = *(const float4*)(g_Q + (size_t)node * DIM + ncol0 + (tx << 2));
    const int hloc = tx >> 3;

    float myscore[8];
    #pragma unroll
    for (int r = 0; r < 8; r++) {
        int e = (ty << 3) + r;
        int m = nb[e];
        float4 k4 = *(const float4*)(g_K + (size_t)m * DIM + ncol0 + (tx << 2));
        float p = acc[r][0] * k4.x * q4.x + acc[r][1] * k4.y * q4.y
                + acc[r][2] * k4.z * q4.z + acc[r][3] * k4.w * q4.w;
        p += __shfl_xor_sync(0xffffffffu, p, 1);
        p += __shfl_xor_sync(0xffffffffu, p, 2);
        p += __shfl_xor_sync(0xffffffffu, p, 4);
        myscore[r] = p;
    }
    if ((tx & 7) == 0) {
        #pragma unroll
        for (int r = 0; r < 8; r++) {
            int e = (ty << 3) + r;
            float s = myscore[r] + e2s[hloc][e];
            s = fminf(fmaxf(s, -8.f), 8.f);
            sc[hloc][e] = s;
        }
    }
    __syncthreads();

    // ---- Phase 3: softmax over deg=32, one warp per (node, head) ---------
    {
        const int warp = tid >> 5, lane = tid & 31;
        const int i = warp >> 1, h = warp & 1;
        float s = sc[h][i * 32 + lane];
        float mx = s;
        #pragma unroll
        for (int o = 16; o; o >>= 1) mx = fmaxf(mx, __shfl_xor_sync(0xffffffffu, mx, o));
        float p = __expf(s - mx);
        float sum = p;
        #pragma unroll
        for (int o = 16; o; o >>= 1) sum += __shfl_xor_sync(0xffffffffu, sum, o);
        sc[h][i * 32 + lane] = p / sum;
    }
    __syncthreads();

    // ---- Phase 4: output, one element per thread -------------------------
    {
        const int i   = tid >> 6;          // local node
        const int rem = tid & 63;
        const int h   = rem >> 5;          // local head
        const int k   = rem & 31;
        const int col = ncol0 + h * 32 + k;
        const float* Vb = g_V + col;
        float acco = 0.f;
        #pragma unroll 8
        for (int d = 0; d < 32; d++) {
            int e = i * 32 + d;
            acco += sc[h][e] * Vb[(size_t)nb[e] * DIM];
        }
        out[(size_t)(tile * 4 + i) * DIM + col] = acco;
    }
}

// ---------------------------------------------------------------------------
extern "C" void kernel_launch(void* const* d_in, const int* in_sizes, int n_in,
                              void* d_out, int out_size)
{
    const float* x   = (const float*)d_in[0];
    const int*   ei  = (const int*)d_in[1];     // int32 (JAX x64 disabled)
    const float* ea  = (const float*)d_in[2];
    const float* WQ  = (const float*)d_in[3];
    const float* WK  = (const float*)d_in[4];
    const float* WV  = (const float*)d_in[5];
    const float* WE1 = (const float*)d_in[6];
    const float* WE2 = (const float*)d_in[7];
    const float* bE2 = (const float*)d_in[8];
    float* out = (float*)d_out;

    qkv_kernel<<<dim3((NN + 63) / 64, DIM / 64, 3), 256>>>(x, WQ, WK, WV);
    edge_kernel<<<dim3(4, NE / 128), 256>>>(ea, ei, WE1, WE2, bE2, out);
}